// round 1
// baseline (speedup 1.0000x reference)
#include <cuda_runtime.h>

#define BB 4
#define EE 1500
#define DD 256
#define HH 8
#define DK 32

#define O_ATTN 1536000
#define O_APE  73536000

// ---------------- scratch (no allocation allowed) ----------------
__device__ float g_q[BB*HH*EE*DK];     // scaled q, [b,h,e,dk]
__device__ float g_k[BB*HH*EE*DK];
__device__ float g_v[BB*HH*EE*DK];
__device__ float g_qdr[BB*HH*EE*8];    // q . base_rpr[p], p padded to 8
__device__ float g_o[BB*EE*DD];        // attention output pre-FC, [b,e,h*32+d]
__device__ float g_asum[BB*EE];
__device__ int   g_acnt[BB*EE];

__device__ __forceinline__ float warp_sum(float v) {
    #pragma unroll
    for (int o = 16; o; o >>= 1) v += __shfl_xor_sync(0xffffffffu, v, o);
    return v;
}
__device__ __forceinline__ float warp_max(float v) {
    #pragma unroll
    for (int o = 16; o; o >>= 1) v = fmaxf(v, __shfl_xor_sync(0xffffffffu, v, o));
    return v;
}

// ---------------- K0: zero accumulators ----------------
__global__ void zero_kernel() {
    int i = blockIdx.x * 256 + threadIdx.x;
    if (i < BB*EE) { g_asum[i] = 0.f; g_acnt[i] = 0; }
}

// ---------------- K1: layernorm + QKV projections + q.rpr ----------------
__global__ void __launch_bounds__(256) proj_kernel(
    const float* __restrict__ x,
    const float* __restrict__ Wq, const float* __restrict__ Wk,
    const float* __restrict__ Wv,
    const float* __restrict__ lnw, const float* __restrict__ lnb,
    const float* __restrict__ rpr)
{
    __shared__ __align__(16) float ssm[256*8];   // [d][r] raw input rows
    __shared__ __align__(16) float nsm[256*8];   // [d][r] layernormed rows
    int b  = blockIdx.y;
    int e0 = blockIdx.x * 8;
    int t  = threadIdx.x;
    const float* xb = x + b*(DD*EE);

    for (int i = t; i < 2048; i += 256) {
        int d = i >> 3, r = i & 7;
        int e = e0 + r;
        ssm[i] = (e < EE) ? xb[d*EE + e] : 0.f;
    }
    __syncthreads();

    int w = t >> 5, lane = t & 31;
    {   // layernorm of row w (one row per warp)
        float s = 0.f;
        #pragma unroll
        for (int i = 0; i < 8; i++) s += ssm[(lane + 32*i)*8 + w];
        s = warp_sum(s);
        float mu = s * (1.f/256.f);
        float vs = 0.f;
        #pragma unroll
        for (int i = 0; i < 8; i++) {
            float dlt = ssm[(lane + 32*i)*8 + w] - mu;
            vs += dlt*dlt;
        }
        vs = warp_sum(vs);
        float rstd = rsqrtf(vs * (1.f/256.f) + 1e-6f);
        #pragma unroll
        for (int i = 0; i < 8; i++) {
            int d = lane + 32*i;
            nsm[d*8 + w] = (ssm[d*8 + w] - mu) * rstd * lnw[d] + lnb[d];
        }
    }
    __syncthreads();

    int j = t;
    float aq[8], ak[8], av[8];
    #pragma unroll
    for (int r = 0; r < 8; r++) { aq[r] = 0.f; ak[r] = 0.f; av[r] = 0.f; }

    #pragma unroll 4
    for (int d = 0; d < 256; d++) {
        float wq = Wq[d*256 + j];
        float wk = Wk[d*256 + j];
        float wv = Wv[d*256 + j];
        float4 s0 = *(const float4*)&ssm[d*8];
        float4 s1 = *(const float4*)&ssm[d*8 + 4];
        float4 n0 = *(const float4*)&nsm[d*8];
        float4 n1 = *(const float4*)&nsm[d*8 + 4];
        aq[0] += n0.x*wq; aq[1] += n0.y*wq; aq[2] += n0.z*wq; aq[3] += n0.w*wq;
        aq[4] += n1.x*wq; aq[5] += n1.y*wq; aq[6] += n1.z*wq; aq[7] += n1.w*wq;
        ak[0] += s0.x*wk; ak[1] += s0.y*wk; ak[2] += s0.z*wk; ak[3] += s0.w*wk;
        ak[4] += s1.x*wk; ak[5] += s1.y*wk; ak[6] += s1.z*wk; ak[7] += s1.w*wk;
        av[0] += s0.x*wv; av[1] += s0.y*wv; av[2] += s0.z*wv; av[3] += s0.w*wv;
        av[4] += s1.x*wv; av[5] += s1.y*wv; av[6] += s1.z*wv; av[7] += s1.w*wv;
    }

    int h = j >> 5, dk = j & 31;
    const float inv_sqrt_dk = 0.17677669529663687f;  // 1/sqrt(32)
    float qsv[8];
    #pragma unroll
    for (int r = 0; r < 8; r++) qsv[r] = aq[r] * inv_sqrt_dk;

    #pragma unroll
    for (int r = 0; r < 8; r++) {
        int e = e0 + r;
        if (e < EE) {
            int base = ((b*HH + h)*EE + e)*32 + dk;
            g_q[base] = qsv[r];
            g_k[base] = ak[r];
            g_v[base] = av[r];
        }
    }

    // qdr[b,h,e,p] = qs . base_rpr[p]   (warp w == head h, lane == dk)
    #pragma unroll
    for (int p = 0; p < 6; p++) {
        float rv = rpr[p*32 + lane];
        #pragma unroll
        for (int r = 0; r < 8; r++) {
            float pv = warp_sum(qsv[r] * rv);
            if (lane == 0 && (e0 + r) < EE)
                g_qdr[((b*HH + h)*EE + (e0 + r))*8 + p] = pv;
        }
    }
}

// ---------------- K2: attention (scores + softmax + attn write + AV + colsums) ----------------
#define SC_LD 1504
#define SMEM_ATTN ((16*SC_LD + 32*65 + 64*33 + 16*32 + 16*8 + 1504)*4 + 1504*4)

__global__ void __launch_bounds__(256) attn_kernel(
    const int* __restrict__ dist, float* __restrict__ out)
{
    extern __shared__ __align__(16) float sm[];
    float* sc     = sm;                    // 16 x 1504 scores -> attn
    float* ksmT   = sc + 16*SC_LD;         // 32 x 65 transposed K chunk
    float* vsm    = ksmT + 32*65;          // 64 x 33 V chunk
    float* qsm    = vsm + 64*33;           // 16 x 32 scaled q
    float* qdr    = qsm + 16*32;           // 16 x 8 bias table
    float* colsum = qdr + 16*8;            // 1504
    int*   colcnt = (int*)(colsum + 1504); // 1504

    int qt = blockIdx.x, h = blockIdx.y, b = blockIdx.z;
    int q0 = qt * 16;
    int t  = threadIdx.x;
    int bh = b*HH + h;
    const float* kbase = g_k + bh*(EE*32);
    const float* vbase = g_v + bh*(EE*32);

    for (int i = t; i < 16*32; i += 256) {
        int qg = q0 + (i >> 5);
        qsm[i] = (qg < EE) ? g_q[(bh*EE + qg)*32 + (i & 31)] : 0.f;
    }
    for (int i = t; i < 16*8; i += 256) {
        int qg = q0 + (i >> 3);
        qdr[i] = (qg < EE) ? g_qdr[(bh*EE + qg)*8 + (i & 7)] : 0.f;
    }
    for (int i = t; i < 1504; i += 256) { colsum[i] = 0.f; colcnt[i] = 0; }
    __syncthreads();

    // ---- score phase ----
    int kk = t & 63, qb = t >> 6;
    const int* distb = dist + b*(EE*EE);
    for (int kc = 0; kc < EE; kc += 64) {
        int cw = min(64, EE - kc);
        for (int i = t; i < cw*32; i += 256) {
            int kkk = i >> 5, d = i & 31;
            ksmT[d*65 + kkk] = kbase[kc*32 + i];
        }
        __syncthreads();
        if (kk < cw) {
            float a0 = 0.f, a1 = 0.f, a2 = 0.f, a3 = 0.f;
            #pragma unroll
            for (int d = 0; d < 32; d += 4) {
                float k0 = ksmT[(d+0)*65 + kk];
                float k1 = ksmT[(d+1)*65 + kk];
                float k2 = ksmT[(d+2)*65 + kk];
                float k3 = ksmT[(d+3)*65 + kk];
                float4 qA = *(const float4*)&qsm[(qb     )*32 + d];
                float4 qB = *(const float4*)&qsm[(qb +  4)*32 + d];
                float4 qC = *(const float4*)&qsm[(qb +  8)*32 + d];
                float4 qD = *(const float4*)&qsm[(qb + 12)*32 + d];
                a0 += k0*qA.x + k1*qA.y + k2*qA.z + k3*qA.w;
                a1 += k0*qB.x + k1*qB.y + k2*qB.z + k3*qB.w;
                a2 += k0*qC.x + k1*qC.y + k2*qC.z + k3*qC.w;
                a3 += k0*qD.x + k1*qD.y + k2*qD.z + k3*qD.w;
            }
            float accs[4] = {a0, a1, a2, a3};
            int kg = kc + kk;
            #pragma unroll
            for (int i = 0; i < 4; i++) {
                int qq = qb + 4*i;
                int qg = q0 + qq;
                float s = -1e9f;
                if (qg < EE) {
                    int dv = distb[qg*EE + kg];
                    if (dv <= 3) {
                        s = accs[i] + qdr[qq*8 + dv];
                        if (h == 0) atomicAdd(&colcnt[kg], 1);
                    }
                }
                sc[qq*SC_LD + kg] = s;
            }
        }
        __syncthreads();
    }

    // ---- softmax + attn write + column sums ----
    int w = t >> 5, lane = t & 31;
    for (int rr = w; rr < 16; rr += 8) {
        int qg = q0 + rr;
        if (qg >= EE) continue;    // warp-uniform
        float* row = sc + rr*SC_LD;
        float m = -3.4e38f;
        for (int k = lane*4; k < EE; k += 128) {
            float4 v = *(const float4*)&row[k];
            m = fmaxf(m, fmaxf(fmaxf(v.x, v.y), fmaxf(v.z, v.w)));
        }
        m = warp_max(m);
        float sum = 0.f;
        for (int k = lane*4; k < EE; k += 128) {
            float4 v = *(float4*)&row[k];
            v.x = __expf(v.x - m); v.y = __expf(v.y - m);
            v.z = __expf(v.z - m); v.w = __expf(v.w - m);
            *(float4*)&row[k] = v;
            sum += (v.x + v.y) + (v.z + v.w);
        }
        sum = warp_sum(sum);
        float inv = 1.f / sum;
        bool fullmask = (m < -1e8f);
        int obase = O_ATTN + (bh*EE + qg)*EE;
        for (int k = lane*4; k < EE; k += 128) {
            float4 v = *(float4*)&row[k];
            v.x *= inv; v.y *= inv; v.z *= inv; v.w *= inv;
            *(float4*)&out[obase + k] = v;
            *(float4*)&row[k] = v;
            if (!fullmask) {
                atomicAdd(&colsum[k+0], v.x);
                atomicAdd(&colsum[k+1], v.y);
                atomicAdd(&colsum[k+2], v.z);
                atomicAdd(&colsum[k+3], v.w);
            }
        }
    }
    __syncthreads();

    // flush column accumulators
    for (int i = t; i < EE; i += 256) {
        atomicAdd(&g_asum[b*EE + i], colsum[i]);
        if (h == 0) atomicAdd(&g_acnt[b*EE + i], colcnt[i]);
    }

    // ---- AV ----
    int dd = t & 31, q1 = t >> 5, q2 = (t >> 5) + 8;
    float accA = 0.f, accB = 0.f;
    for (int kc = 0; kc < EE; kc += 64) {
        int cw = min(64, EE - kc);
        __syncthreads();
        for (int i = t; i < cw*32; i += 256) {
            int kkk = i >> 5, d = i & 31;
            vsm[kkk*33 + d] = vbase[kc*32 + i];
        }
        __syncthreads();
        for (int k4 = 0; k4 < cw; k4 += 4) {
            float4 x1 = *(const float4*)&sc[q1*SC_LD + kc + k4];
            float4 x2 = *(const float4*)&sc[q2*SC_LD + kc + k4];
            float v0 = vsm[(k4+0)*33 + dd];
            float v1 = vsm[(k4+1)*33 + dd];
            float v2 = vsm[(k4+2)*33 + dd];
            float v3 = vsm[(k4+3)*33 + dd];
            accA += x1.x*v0 + x1.y*v1 + x1.z*v2 + x1.w*v3;
            accB += x2.x*v0 + x2.y*v1 + x2.z*v2 + x2.w*v3;
        }
    }
    if (q0 + q1 < EE) g_o[(b*EE + q0 + q1)*DD + h*32 + dd] = accA;
    if (q0 + q2 < EE) g_o[(b*EE + q0 + q2)*DD + h*32 + dd] = accB;
}

// ---------------- K3: FC + residual + transpose-out ----------------
__global__ void __launch_bounds__(256) fc_kernel(
    const float* __restrict__ x, const float* __restrict__ Wfc,
    float* __restrict__ out)
{
    __shared__ __align__(16) float osm[256*8];   // [d][r]
    int b  = blockIdx.y;
    int e0 = blockIdx.x * 8;
    int t  = threadIdx.x;

    for (int i = t; i < 2048; i += 256) {
        int r = i >> 8, d = i & 255;
        int e = e0 + r;
        osm[d*8 + r] = (e < EE) ? g_o[(b*EE + e)*DD + d] : 0.f;
    }
    __syncthreads();

    int j = t;
    const float* xb = x + b*DD*EE + j*EE;
    float acc[8];
    #pragma unroll
    for (int r = 0; r < 8; r++) {
        int e = e0 + r;
        acc[r] = (e < EE) ? xb[e] : 0.f;   // residual
    }
    #pragma unroll 4
    for (int d = 0; d < 256; d++) {
        float wv = Wfc[d*256 + j];
        float4 o0 = *(const float4*)&osm[d*8];
        float4 o1 = *(const float4*)&osm[d*8 + 4];
        acc[0] += o0.x*wv; acc[1] += o0.y*wv; acc[2] += o0.z*wv; acc[3] += o0.w*wv;
        acc[4] += o1.x*wv; acc[5] += o1.y*wv; acc[6] += o1.z*wv; acc[7] += o1.w*wv;
    }
    float* ob = out + b*DD*EE + j*EE + e0;
    if (e0 + 8 <= EE) {
        *(float4*)ob       = make_float4(acc[0], acc[1], acc[2], acc[3]);
        *(float4*)(ob + 4) = make_float4(acc[4], acc[5], acc[6], acc[7]);
    } else {
        for (int r = 0; r < 8; r++)
            if (e0 + r < EE) ob[r] = acc[r];
    }
}

// ---------------- K4: attn_per_edge ----------------
__global__ void finalize_kernel(float* __restrict__ out) {
    int i = blockIdx.x * 256 + threadIdx.x;
    if (i < BB*EE) {
        int c = g_acnt[i];
        out[O_APE + i] = g_asum[i] / (float)c;
    }
}

// ---------------- launch ----------------
extern "C" void kernel_launch(void* const* d_in, const int* in_sizes, int n_in,
                              void* d_out, int out_size)
{
    const float* x    = (const float*)d_in[0];
    const int*   dist = (const int*)  d_in[1];
    const float* Wq   = (const float*)d_in[2];
    const float* Wk   = (const float*)d_in[3];
    const float* Wv   = (const float*)d_in[4];
    const float* Wfc  = (const float*)d_in[5];
    const float* lnw  = (const float*)d_in[6];
    const float* lnb  = (const float*)d_in[7];
    const float* rpr  = (const float*)d_in[8];
    float* out = (float*)d_out;

    cudaFuncSetAttribute(attn_kernel,
        cudaFuncAttributeMaxDynamicSharedMemorySize, SMEM_ATTN);

    zero_kernel<<<24, 256>>>();

    dim3 g1(188, BB);
    proj_kernel<<<g1, 256>>>(x, Wq, Wk, Wv, lnw, lnb, rpr);

    dim3 g2(94, HH, BB);
    attn_kernel<<<g2, 256, SMEM_ATTN>>>(dist, out);

    dim3 g3(188, BB);
    fc_kernel<<<g3, 256>>>(x, Wfc, out);

    finalize_kernel<<<24, 256>>>(out);
}

// round 2
// speedup vs baseline: 1.8381x; 1.8381x over previous
#include <cuda_runtime.h>

#define BB 4
#define EE 1500
#define DD 256
#define HH 8
#define DK 32

#define O_ATTN 1536000
#define O_APE  73536000

// ---------------- scratch (no allocation allowed) ----------------
__device__ float g_q[BB*HH*EE*DK];     // scaled q, [b,h,e,dk]
__device__ float g_k[BB*HH*EE*DK];
__device__ float g_v[BB*HH*EE*DK];
__device__ float g_qdr[BB*HH*EE*8];    // q . base_rpr[p], p padded to 8
__device__ float g_o[BB*EE*DD];        // attention output pre-FC, [b,e,h*32+d]
__device__ float g_asum[BB*EE];
__device__ int   g_acnt[BB*EE];

__device__ __forceinline__ float warp_sum(float v) {
    #pragma unroll
    for (int o = 16; o; o >>= 1) v += __shfl_xor_sync(0xffffffffu, v, o);
    return v;
}
__device__ __forceinline__ float warp_max(float v) {
    #pragma unroll
    for (int o = 16; o; o >>= 1) v = fmaxf(v, __shfl_xor_sync(0xffffffffu, v, o));
    return v;
}

// ---------------- K0: zero accumulators ----------------
__global__ void zero_kernel() {
    int i = blockIdx.x * 256 + threadIdx.x;
    if (i < BB*EE) { g_asum[i] = 0.f; g_acnt[i] = 0; }
}

// ---------------- K0b: valid-edge counts from dist ----------------
__global__ void count_kernel(const int* __restrict__ dist) {
    int i = blockIdx.x * 256 + threadIdx.x;   // b*EE + e
    if (i >= BB*EE) return;
    int b = i / EE, e = i - b*EE;
    int q0 = blockIdx.y * 188;
    int q1 = min(EE, q0 + 188);
    const int* dp = dist + (long long)b*EE*EE + e;
    int c = 0;
    #pragma unroll 4
    for (int q = q0; q < q1; q++) c += (dp[q*EE] <= 3) ? 1 : 0;
    atomicAdd(&g_acnt[i], c);
}

// ---------------- K1: layernorm + QKV projections + q.rpr ----------------
__global__ void __launch_bounds__(256) proj_kernel(
    const float* __restrict__ x,
    const float* __restrict__ Wq, const float* __restrict__ Wk,
    const float* __restrict__ Wv,
    const float* __restrict__ lnw, const float* __restrict__ lnb,
    const float* __restrict__ rpr)
{
    __shared__ __align__(16) float ssm[256*8];   // [d][r] raw input rows
    __shared__ __align__(16) float nsm[256*8];   // [d][r] layernormed rows
    int b  = blockIdx.y;
    int e0 = blockIdx.x * 8;
    int t  = threadIdx.x;
    const float* xb = x + b*(DD*EE);

    for (int i = t; i < 2048; i += 256) {
        int d = i >> 3, r = i & 7;
        int e = e0 + r;
        ssm[i] = (e < EE) ? xb[d*EE + e] : 0.f;
    }
    __syncthreads();

    int w = t >> 5, lane = t & 31;
    {   // layernorm of row w (one row per warp)
        float s = 0.f;
        #pragma unroll
        for (int i = 0; i < 8; i++) s += ssm[(lane + 32*i)*8 + w];
        s = warp_sum(s);
        float mu = s * (1.f/256.f);
        float vs = 0.f;
        #pragma unroll
        for (int i = 0; i < 8; i++) {
            float dlt = ssm[(lane + 32*i)*8 + w] - mu;
            vs += dlt*dlt;
        }
        vs = warp_sum(vs);
        float rstd = rsqrtf(vs * (1.f/256.f) + 1e-6f);
        #pragma unroll
        for (int i = 0; i < 8; i++) {
            int d = lane + 32*i;
            nsm[d*8 + w] = (ssm[d*8 + w] - mu) * rstd * lnw[d] + lnb[d];
        }
    }
    __syncthreads();

    int j = t;
    float aq[8], ak[8], av[8];
    #pragma unroll
    for (int r = 0; r < 8; r++) { aq[r] = 0.f; ak[r] = 0.f; av[r] = 0.f; }

    #pragma unroll 4
    for (int d = 0; d < 256; d++) {
        float wq = Wq[d*256 + j];
        float wk = Wk[d*256 + j];
        float wv = Wv[d*256 + j];
        float4 s0 = *(const float4*)&ssm[d*8];
        float4 s1 = *(const float4*)&ssm[d*8 + 4];
        float4 n0 = *(const float4*)&nsm[d*8];
        float4 n1 = *(const float4*)&nsm[d*8 + 4];
        aq[0] += n0.x*wq; aq[1] += n0.y*wq; aq[2] += n0.z*wq; aq[3] += n0.w*wq;
        aq[4] += n1.x*wq; aq[5] += n1.y*wq; aq[6] += n1.z*wq; aq[7] += n1.w*wq;
        ak[0] += s0.x*wk; ak[1] += s0.y*wk; ak[2] += s0.z*wk; ak[3] += s0.w*wk;
        ak[4] += s1.x*wk; ak[5] += s1.y*wk; ak[6] += s1.z*wk; ak[7] += s1.w*wk;
        av[0] += s0.x*wv; av[1] += s0.y*wv; av[2] += s0.z*wv; av[3] += s0.w*wv;
        av[4] += s1.x*wv; av[5] += s1.y*wv; av[6] += s1.z*wv; av[7] += s1.w*wv;
    }

    int h = j >> 5, dk = j & 31;
    const float inv_sqrt_dk = 0.17677669529663687f;  // 1/sqrt(32)
    float qsv[8];
    #pragma unroll
    for (int r = 0; r < 8; r++) qsv[r] = aq[r] * inv_sqrt_dk;

    #pragma unroll
    for (int r = 0; r < 8; r++) {
        int e = e0 + r;
        if (e < EE) {
            int base = ((b*HH + h)*EE + e)*32 + dk;
            g_q[base] = qsv[r];
            g_k[base] = ak[r];
            g_v[base] = av[r];
        }
    }

    // qdr[b,h,e,p] = qs . base_rpr[p]   (warp w == head h, lane == dk)
    #pragma unroll
    for (int p = 0; p < 6; p++) {
        float rv = rpr[p*32 + lane];
        #pragma unroll
        for (int r = 0; r < 8; r++) {
            float pv = warp_sum(qsv[r] * rv);
            if (lane == 0 && (e0 + r) < EE)
                g_qdr[((b*HH + h)*EE + (e0 + r))*8 + p] = pv;
        }
    }
}

// ---------------- K2: attention ----------------
#define SC_LD 1504
#define KV_FLOATS 4224          // max(32*129 K-transposed, 128*33 V, 2048 partials)
#define SMEM_ATTN ((16*SC_LD + KV_FLOATS + 16*32 + 16*8 + 16)*4)

__global__ void __launch_bounds__(512) attn_kernel(
    const int* __restrict__ dist, float* __restrict__ out)
{
    extern __shared__ __align__(16) float sm[];
    float* sc   = sm;                    // 16 x 1504 scores -> attn (normalized)
    float* kv   = sc + 16*SC_LD;         // K chunk (transposed) / V chunk / AV partials
    float* qsm  = kv + KV_FLOATS;        // 16 x 32 scaled q
    float* qdr  = qsm + 16*32;           // 16 x 8 bias table
    float* flag = qdr + 16*8;            // 16 row-valid flags

    int qt = blockIdx.x, h = blockIdx.y, b = blockIdx.z;
    int q0 = qt * 16;
    int t  = threadIdx.x;
    int bh = b*HH + h;
    const float* kbase = g_k + bh*(EE*32);
    const float* vbase = g_v + bh*(EE*32);

    for (int i = t; i < 16*32; i += 512) {
        int qg = q0 + (i >> 5);
        qsm[i] = (qg < EE) ? g_q[(bh*EE + qg)*32 + (i & 31)] : 0.f;
    }
    if (t < 16*8) {
        int qg = q0 + (t >> 3);
        qdr[t] = (qg < EE) ? g_qdr[(bh*EE + qg)*8 + (t & 7)] : 0.f;
    }
    __syncthreads();

    // ---- score phase: chunks of 128 k-columns ----
    int kk = t & 127, qb = t >> 7;       // qb in 0..3; rows qb, qb+4, qb+8, qb+12
    const int* distb = dist + (long long)b*(EE*EE);
    for (int kc = 0; kc < EE; kc += 128) {
        int cw = min(128, EE - kc);
        for (int i4 = t; i4 < cw*8; i4 += 512) {
            int kr = i4 >> 3, d0 = (i4 & 7) * 4;
            float4 kvv = *(const float4*)&kbase[(kc + kr)*32 + d0];
            kv[(d0+0)*129 + kr] = kvv.x;
            kv[(d0+1)*129 + kr] = kvv.y;
            kv[(d0+2)*129 + kr] = kvv.z;
            kv[(d0+3)*129 + kr] = kvv.w;
        }
        __syncthreads();
        if (kk < cw) {
            float a0 = 0.f, a1 = 0.f, a2 = 0.f, a3 = 0.f;
            #pragma unroll
            for (int d = 0; d < 32; d += 4) {
                float k0 = kv[(d+0)*129 + kk];
                float k1 = kv[(d+1)*129 + kk];
                float k2 = kv[(d+2)*129 + kk];
                float k3 = kv[(d+3)*129 + kk];
                float4 qA = *(const float4*)&qsm[(qb     )*32 + d];
                float4 qB = *(const float4*)&qsm[(qb +  4)*32 + d];
                float4 qC = *(const float4*)&qsm[(qb +  8)*32 + d];
                float4 qD = *(const float4*)&qsm[(qb + 12)*32 + d];
                a0 += k0*qA.x + k1*qA.y + k2*qA.z + k3*qA.w;
                a1 += k0*qB.x + k1*qB.y + k2*qB.z + k3*qB.w;
                a2 += k0*qC.x + k1*qC.y + k2*qC.z + k3*qC.w;
                a3 += k0*qD.x + k1*qD.y + k2*qD.z + k3*qD.w;
            }
            float accs[4] = {a0, a1, a2, a3};
            int kg = kc + kk;
            #pragma unroll
            for (int i = 0; i < 4; i++) {
                int qq = qb + 4*i;
                int qg = q0 + qq;
                float s = -1e9f;
                if (qg < EE) {
                    int dv = distb[qg*EE + kg];
                    if (dv <= 3) s = accs[i] + qdr[qq*8 + dv];
                }
                sc[qq*SC_LD + kg] = s;
            }
        }
        __syncthreads();
    }

    // ---- softmax (one row per warp) + attn global write ----
    int w = t >> 5, lane = t & 31;
    {
        int rr = w;
        int qg = q0 + rr;
        if (qg < EE) {
            float* row = sc + rr*SC_LD;
            float m = -3.4e38f;
            for (int k = lane*4; k < EE; k += 128) {
                float4 v = *(const float4*)&row[k];
                m = fmaxf(m, fmaxf(fmaxf(v.x, v.y), fmaxf(v.z, v.w)));
            }
            m = warp_max(m);
            float sum = 0.f;
            for (int k = lane*4; k < EE; k += 128) {
                float4 v = *(float4*)&row[k];
                v.x = __expf(v.x - m); v.y = __expf(v.y - m);
                v.z = __expf(v.z - m); v.w = __expf(v.w - m);
                *(float4*)&row[k] = v;
                sum += (v.x + v.y) + (v.z + v.w);
            }
            sum = warp_sum(sum);
            float inv = 1.f / sum;
            bool fullmask = (m < -1e8f);
            if (lane == 0) flag[rr] = fullmask ? 0.f : 1.f;
            long long obase = (long long)O_ATTN + (long long)(bh*EE + qg)*EE;
            for (int k = lane*4; k < EE; k += 128) {
                float4 v = *(float4*)&row[k];
                v.x *= inv; v.y *= inv; v.z *= inv; v.w *= inv;
                *(float4*)&out[obase + k] = v;
                *(float4*)&row[k] = v;
            }
        } else {
            if (lane == 0) flag[rr] = 0.f;
        }
    }
    __syncthreads();

    // ---- column sums (no atomics within tile; one REDG per column) ----
    for (int k = t; k < EE; k += 512) {
        float s = 0.f;
        #pragma unroll
        for (int r = 0; r < 16; r++) s += sc[r*SC_LD + k] * flag[r];
        atomicAdd(&g_asum[b*EE + k], s);
    }

    // ---- AV: warp = (k-quarter, row-group), 4 rows per thread ----
    int dd   = t & 31;
    int qgrp = w & 3;            // rows qgrp, qgrp+4, qgrp+8, qgrp+12
    int ksub = w >> 2;           // quarter of each 128-chunk
    float acc0 = 0.f, acc1 = 0.f, acc2 = 0.f, acc3 = 0.f;
    for (int kc = 0; kc < EE; kc += 128) {
        int cw = min(128, EE - kc);
        for (int i4 = t; i4 < cw*8; i4 += 512) {
            int kr = i4 >> 3, d0 = (i4 & 7) * 4;
            float4 vv = *(const float4*)&vbase[(kc + kr)*32 + d0];
            kv[kr*33 + d0+0] = vv.x;
            kv[kr*33 + d0+1] = vv.y;
            kv[kr*33 + d0+2] = vv.z;
            kv[kr*33 + d0+3] = vv.w;
        }
        __syncthreads();
        int kbeg = ksub*32, kend = min(cw, kbeg + 32);
        for (int k4 = kbeg; k4 < kend; k4 += 4) {
            float v0 = kv[(k4+0)*33 + dd];
            float v1 = kv[(k4+1)*33 + dd];
            float v2 = kv[(k4+2)*33 + dd];
            float v3 = kv[(k4+3)*33 + dd];
            float4 aA = *(const float4*)&sc[(qgrp     )*SC_LD + kc + k4];
            float4 aB = *(const float4*)&sc[(qgrp +  4)*SC_LD + kc + k4];
            float4 aC = *(const float4*)&sc[(qgrp +  8)*SC_LD + kc + k4];
            float4 aD = *(const float4*)&sc[(qgrp + 12)*SC_LD + kc + k4];
            acc0 += aA.x*v0 + aA.y*v1 + aA.z*v2 + aA.w*v3;
            acc1 += aB.x*v0 + aB.y*v1 + aB.z*v2 + aB.w*v3;
            acc2 += aC.x*v0 + aC.y*v1 + aC.z*v2 + aC.w*v3;
            acc3 += aD.x*v0 + aD.y*v1 + aD.z*v2 + aD.w*v3;
        }
        __syncthreads();
    }
    // combine the 4 k-partitions
    kv[ksub*512 + (qgrp     )*32 + dd] = acc0;
    kv[ksub*512 + (qgrp +  4)*32 + dd] = acc1;
    kv[ksub*512 + (qgrp +  8)*32 + dd] = acc2;
    kv[ksub*512 + (qgrp + 12)*32 + dd] = acc3;
    __syncthreads();
    {
        int q = t >> 5;          // 0..15
        float s = kv[q*32 + dd] + kv[512 + q*32 + dd]
                + kv[1024 + q*32 + dd] + kv[1536 + q*32 + dd];
        if (q0 + q < EE) g_o[(b*EE + q0 + q)*DD + h*32 + dd] = s;
    }
}

// ---------------- K3: FC + residual + transpose-out ----------------
__global__ void __launch_bounds__(256) fc_kernel(
    const float* __restrict__ x, const float* __restrict__ Wfc,
    float* __restrict__ out)
{
    __shared__ __align__(16) float osm[256*8];   // [d][r]
    int b  = blockIdx.y;
    int e0 = blockIdx.x * 8;
    int t  = threadIdx.x;

    for (int i = t; i < 2048; i += 256) {
        int r = i >> 8, d = i & 255;
        int e = e0 + r;
        osm[d*8 + r] = (e < EE) ? g_o[(b*EE + e)*DD + d] : 0.f;
    }
    __syncthreads();

    int j = t;
    const float* xb = x + b*DD*EE + j*EE;
    float acc[8];
    #pragma unroll
    for (int r = 0; r < 8; r++) {
        int e = e0 + r;
        acc[r] = (e < EE) ? xb[e] : 0.f;   // residual
    }
    #pragma unroll 4
    for (int d = 0; d < 256; d++) {
        float wv = Wfc[d*256 + j];
        float4 o0 = *(const float4*)&osm[d*8];
        float4 o1 = *(const float4*)&osm[d*8 + 4];
        acc[0] += o0.x*wv; acc[1] += o0.y*wv; acc[2] += o0.z*wv; acc[3] += o0.w*wv;
        acc[4] += o1.x*wv; acc[5] += o1.y*wv; acc[6] += o1.z*wv; acc[7] += o1.w*wv;
    }
    float* ob = out + b*DD*EE + j*EE + e0;
    if (e0 + 8 <= EE) {
        *(float4*)ob       = make_float4(acc[0], acc[1], acc[2], acc[3]);
        *(float4*)(ob + 4) = make_float4(acc[4], acc[5], acc[6], acc[7]);
    } else {
        for (int r = 0; r < 8; r++)
            if (e0 + r < EE) ob[r] = acc[r];
    }
}

// ---------------- K4: attn_per_edge ----------------
__global__ void finalize_kernel(float* __restrict__ out) {
    int i = blockIdx.x * 256 + threadIdx.x;
    if (i < BB*EE) {
        out[O_APE + i] = g_asum[i] / (float)g_acnt[i];
    }
}

// ---------------- launch ----------------
extern "C" void kernel_launch(void* const* d_in, const int* in_sizes, int n_in,
                              void* d_out, int out_size)
{
    const float* x    = (const float*)d_in[0];
    const int*   dist = (const int*)  d_in[1];
    const float* Wq   = (const float*)d_in[2];
    const float* Wk   = (const float*)d_in[3];
    const float* Wv   = (const float*)d_in[4];
    const float* Wfc  = (const float*)d_in[5];
    const float* lnw  = (const float*)d_in[6];
    const float* lnb  = (const float*)d_in[7];
    const float* rpr  = (const float*)d_in[8];
    float* out = (float*)d_out;

    cudaFuncSetAttribute(attn_kernel,
        cudaFuncAttributeMaxDynamicSharedMemorySize, SMEM_ATTN);

    zero_kernel<<<24, 256>>>();

    dim3 gc(24, 8);
    count_kernel<<<gc, 256>>>(dist);

    dim3 g1(188, BB);
    proj_kernel<<<g1, 256>>>(x, Wq, Wk, Wv, lnw, lnb, rpr);

    dim3 g2(94, HH, BB);
    attn_kernel<<<g2, 512, SMEM_ATTN>>>(dist, out);

    dim3 g3(188, BB);
    fc_kernel<<<g3, 256>>>(x, Wfc, out);

    finalize_kernel<<<24, 256>>>(out);
}

// round 3
// speedup vs baseline: 2.7958x; 1.5210x over previous
#include <cuda_runtime.h>

#define BB 4
#define EE 1500
#define DD 256
#define HH 8
#define DK 32

#define O_ATTN 1536000
#define O_APE  73536000

typedef unsigned long long ull;

// ---------------- scratch (no allocation allowed) ----------------
__device__ float g_q[BB*HH*EE*DK];     // scaled q, [b,h,e,dk]
__device__ float g_k[BB*HH*EE*DK];
__device__ float g_v[BB*HH*EE*DK];
__device__ float g_qdr[BB*HH*EE*8];    // q . base_rpr[p], p padded to 8
__device__ float g_o[BB*EE*DD];        // attention output pre-FC, [b,e,h*32+d]
__device__ float g_asum[BB*EE];
__device__ int   g_acnt[BB*EE];

__device__ __forceinline__ float warp_sum(float v) {
    #pragma unroll
    for (int o = 16; o; o >>= 1) v += __shfl_xor_sync(0xffffffffu, v, o);
    return v;
}
__device__ __forceinline__ float warp_max(float v) {
    #pragma unroll
    for (int o = 16; o; o >>= 1) v = fmaxf(v, __shfl_xor_sync(0xffffffffu, v, o));
    return v;
}

// packed f32x2 helpers (sm_100+)
__device__ __forceinline__ void fma2(ull &d, ull a, ull b) {
    asm("fma.rn.f32x2 %0, %1, %2, %0;" : "+l"(d) : "l"(a), "l"(b));
}
__device__ __forceinline__ float f2sum(ull u) {
    float lo, hi;
    asm("mov.b64 {%0,%1}, %2;" : "=f"(lo), "=f"(hi) : "l"(u));
    return lo + hi;
}
__device__ __forceinline__ ull packf2(float x, float y) {
    ull u;
    asm("mov.b64 %0, {%1,%2};" : "=l"(u) : "f"(x), "f"(y));
    return u;
}

// ---------------- K0: zero accumulators ----------------
__global__ void zero_kernel() {
    int i = blockIdx.x * 256 + threadIdx.x;
    if (i < BB*EE) { g_asum[i] = 0.f; g_acnt[i] = 0; }
}

// ---------------- K0b: valid-edge counts from dist ----------------
__global__ void count_kernel(const int* __restrict__ dist) {
    int i = blockIdx.x * 256 + threadIdx.x;   // b*EE + e
    if (i >= BB*EE) return;
    int b = i / EE, e = i - b*EE;
    int q0 = blockIdx.y * 188;
    int q1 = min(EE, q0 + 188);
    const int* dp = dist + (long long)b*EE*EE + e;
    int c = 0;
    #pragma unroll 4
    for (int q = q0; q < q1; q++) c += (dp[q*EE] <= 3) ? 1 : 0;
    atomicAdd(&g_acnt[i], c);
}

// ---------------- K1: layernorm + QKV projections + q.rpr ----------------
__global__ void __launch_bounds__(256) proj_kernel(
    const float* __restrict__ x,
    const float* __restrict__ Wq, const float* __restrict__ Wk,
    const float* __restrict__ Wv,
    const float* __restrict__ lnw, const float* __restrict__ lnb,
    const float* __restrict__ rpr)
{
    __shared__ __align__(16) float ssm[256*8];   // [d][r] raw input rows
    __shared__ __align__(16) float nsm[256*8];   // [d][r] layernormed rows
    int b  = blockIdx.y;
    int e0 = blockIdx.x * 8;
    int t  = threadIdx.x;
    const float* xb = x + b*(DD*EE);

    for (int i = t; i < 2048; i += 256) {
        int d = i >> 3, r = i & 7;
        int e = e0 + r;
        ssm[i] = (e < EE) ? xb[d*EE + e] : 0.f;
    }
    __syncthreads();

    int w = t >> 5, lane = t & 31;
    {   // layernorm of row w (one row per warp)
        float s = 0.f;
        #pragma unroll
        for (int i = 0; i < 8; i++) s += ssm[(lane + 32*i)*8 + w];
        s = warp_sum(s);
        float mu = s * (1.f/256.f);
        float vs = 0.f;
        #pragma unroll
        for (int i = 0; i < 8; i++) {
            float dlt = ssm[(lane + 32*i)*8 + w] - mu;
            vs += dlt*dlt;
        }
        vs = warp_sum(vs);
        float rstd = rsqrtf(vs * (1.f/256.f) + 1e-6f);
        #pragma unroll
        for (int i = 0; i < 8; i++) {
            int d = lane + 32*i;
            nsm[d*8 + w] = (ssm[d*8 + w] - mu) * rstd * lnw[d] + lnb[d];
        }
    }
    __syncthreads();

    int j = t;
    float aq[8], ak[8], av[8];
    #pragma unroll
    for (int r = 0; r < 8; r++) { aq[r] = 0.f; ak[r] = 0.f; av[r] = 0.f; }

    #pragma unroll 4
    for (int d = 0; d < 256; d++) {
        float wq = Wq[d*256 + j];
        float wk = Wk[d*256 + j];
        float wv = Wv[d*256 + j];
        float4 s0 = *(const float4*)&ssm[d*8];
        float4 s1 = *(const float4*)&ssm[d*8 + 4];
        float4 n0 = *(const float4*)&nsm[d*8];
        float4 n1 = *(const float4*)&nsm[d*8 + 4];
        aq[0] += n0.x*wq; aq[1] += n0.y*wq; aq[2] += n0.z*wq; aq[3] += n0.w*wq;
        aq[4] += n1.x*wq; aq[5] += n1.y*wq; aq[6] += n1.z*wq; aq[7] += n1.w*wq;
        ak[0] += s0.x*wk; ak[1] += s0.y*wk; ak[2] += s0.z*wk; ak[3] += s0.w*wk;
        ak[4] += s1.x*wk; ak[5] += s1.y*wk; ak[6] += s1.z*wk; ak[7] += s1.w*wk;
        av[0] += s0.x*wv; av[1] += s0.y*wv; av[2] += s0.z*wv; av[3] += s0.w*wv;
        av[4] += s1.x*wv; av[5] += s1.y*wv; av[6] += s1.z*wv; av[7] += s1.w*wv;
    }

    int h = j >> 5, dk = j & 31;
    const float inv_sqrt_dk = 0.17677669529663687f;  // 1/sqrt(32)
    float qsv[8];
    #pragma unroll
    for (int r = 0; r < 8; r++) qsv[r] = aq[r] * inv_sqrt_dk;

    #pragma unroll
    for (int r = 0; r < 8; r++) {
        int e = e0 + r;
        if (e < EE) {
            int base = ((b*HH + h)*EE + e)*32 + dk;
            g_q[base] = qsv[r];
            g_k[base] = ak[r];
            g_v[base] = av[r];
        }
    }

    #pragma unroll
    for (int p = 0; p < 6; p++) {
        float rv = rpr[p*32 + lane];
        #pragma unroll
        for (int r = 0; r < 8; r++) {
            float pv = warp_sum(qsv[r] * rv);
            if (lane == 0 && (e0 + r) < EE)
                g_qdr[((b*HH + h)*EE + (e0 + r))*8 + p] = pv;
        }
    }
}

// ---------------- K2: attention ----------------
#define SC_LD 1504
// floats: sc 24064 + buf0 4096 + buf1 4096 + qsm 512 + qdr 128 + flag 16
#define SMEM_ATTN ((16*SC_LD + 4096 + 4096 + 512 + 128 + 16)*4)

__global__ void __launch_bounds__(512, 1) attn_kernel(
    const int* __restrict__ dist, float* __restrict__ out)
{
    extern __shared__ __align__(16) float sm[];
    float* sc   = sm;                    // 16 x 1504 scores -> attn (normalized)
    float* buf0 = sc + 16*SC_LD;         // 4096: K chunk [k][d] / V-T [d][k] / partials
    float* buf1 = buf0 + 4096;
    float* qsm  = buf1 + 4096;           // 16 x 32 scaled q
    float* qdr  = qsm + 512;             // 16 x 8 bias table
    float* flag = qdr + 128;             // 16 row-valid flags

    int qt = blockIdx.x, h = blockIdx.y, b = blockIdx.z;
    int q0 = qt * 16;
    int t  = threadIdx.x;
    int bh = b*HH + h;
    const float* kbase = g_k + bh*(EE*32);
    const float* vbase = g_v + bh*(EE*32);

    for (int i = t; i < 16*32; i += 512) {
        int qg = q0 + (i >> 5);
        qsm[i] = (qg < EE) ? g_q[(bh*EE + qg)*32 + (i & 31)] : 0.f;
    }
    if (t < 16*8) {
        int qg = q0 + (t >> 3);
        qdr[t] = (qg < EE) ? g_qdr[(bh*EE + qg)*8 + (t & 7)] : 0.f;
    }
    __syncthreads();

    // ================= score phase =================
    // thread cells: q in {qpA, qpA+8}, k-cols in {kcA, kcA+64} (per 128-chunk)
    const int* distb = dist + (long long)b*(EE*EE);
    int kcA = t & 63;
    int qpA = t >> 6, qpB = qpA + 8;
    int qgA = q0 + qpA, qgB = q0 + qpB;

    // Q rows into registers (broadcast LDS64, once)
    ull qA[16], qB[16];
    {
        const ull* qrA = (const ull*)(qsm + qpA*32);
        const ull* qrB = (const ull*)(qsm + qpB*32);
        #pragma unroll
        for (int j = 0; j < 16; j++) { qA[j] = qrA[j]; qB[j] = qrB[j]; }
    }

    int xA8 = (kcA & 15);   // swizzle mask (same for kcA and kcA+64)

    // prologue: prefetch chunk 0 (K + dist)
    float4 p0, p1; bool v0, v1;
    int dAa, dAb, dBa, dBb;
    {
        int cw = 128;
        v0 = (t       < cw*8);
        v1 = (t + 512 < cw*8);
        p0 = *(const float4*)&kbase[t*4];
        p1 = *(const float4*)&kbase[(t + 512)*4];
        int kgA = kcA, kgB = kcA + 64;
        dAa = (qgA < EE) ? distb[qgA*EE + kgA] : 99;
        dAb = (qgA < EE) ? distb[qgA*EE + kgB] : 99;
        dBa = (qgB < EE) ? distb[qgB*EE + kgA] : 99;
        dBb = (qgB < EE) ? distb[qgB*EE + kgB] : 99;
    }

    for (int c = 0; c < 12; c++) {
        int kc = c * 128;
        float* bp = (c & 1) ? buf1 : buf0;
        // store current chunk K into smem, swizzled [k][d]
        if (v0) {
            int kr = t >> 3, u0 = (t & 7)*2, xm = kr & 15;
            *(ull*)&bp[kr*32 + ((u0     ^ xm)<<1)] = packf2(p0.x, p0.y);
            *(ull*)&bp[kr*32 + (((u0+1) ^ xm)<<1)] = packf2(p0.z, p0.w);
        }
        if (v1) {
            int i4 = t + 512;
            int kr = i4 >> 3, u0 = (i4 & 7)*2, xm = kr & 15;
            *(ull*)&bp[kr*32 + ((u0     ^ xm)<<1)] = packf2(p1.x, p1.y);
            *(ull*)&bp[kr*32 + (((u0+1) ^ xm)<<1)] = packf2(p1.z, p1.w);
        }
        __syncthreads();

        // prefetch chunk c+1
        float4 n0 = p0, n1 = p1; bool w0 = false, w1 = false;
        int nAa = 99, nAb = 99, nBa = 99, nBb = 99;
        if (c < 11) {
            int kc2 = kc + 128, cw2 = min(128, EE - kc2);
            w0 = (t       < cw2*8);
            w1 = (t + 512 < cw2*8);
            if (w0) n0 = *(const float4*)&kbase[kc2*32 + t*4];
            if (w1) n1 = *(const float4*)&kbase[kc2*32 + (t+512)*4];
            int kg2A = kc2 + kcA, kg2B = kg2A + 64;
            if (qgA < EE && kg2A < EE) nAa = distb[qgA*EE + kg2A];
            if (qgA < EE && kg2B < EE) nAb = distb[qgA*EE + kg2B];
            if (qgB < EE && kg2A < EE) nBa = distb[qgB*EE + kg2A];
            if (qgB < EE && kg2B < EE) nBb = distb[qgB*EE + kg2B];
        }

        // compute 4 cells over 32 d (16 f32x2 pairs)
        const ull* rA = (const ull*)bp + kcA*16;
        const ull* rB = rA + 64*16;
        ull aAA = 0, aAB = 0, aBA = 0, aBB = 0;
        #pragma unroll
        for (int j = 0; j < 16; j++) {
            ull ka = rA[j ^ xA8];
            ull kb = rB[j ^ xA8];
            fma2(aAA, qA[j], ka); fma2(aAB, qA[j], kb);
            fma2(aBA, qB[j], ka); fma2(aBB, qB[j], kb);
        }

        // epilogue: bias + mask + store
        int kgA = kc + kcA, kgB = kgA + 64;
        if (kgA < EE) {
            float s = -1e9f;
            if (dAa <= 3) s = f2sum(aAA) + qdr[qpA*8 + dAa];
            sc[qpA*SC_LD + kgA] = s;
            s = -1e9f;
            if (dBa <= 3) s = f2sum(aBA) + qdr[qpB*8 + dBa];
            sc[qpB*SC_LD + kgA] = s;
        }
        if (kgB < EE) {
            float s = -1e9f;
            if (dAb <= 3) s = f2sum(aAB) + qdr[qpA*8 + dAb];
            sc[qpA*SC_LD + kgB] = s;
            s = -1e9f;
            if (dBb <= 3) s = f2sum(aBB) + qdr[qpB*8 + dBb];
            sc[qpB*SC_LD + kgB] = s;
        }

        p0 = n0; p1 = n1; v0 = w0; v1 = w1;
        dAa = nAa; dAb = nAb; dBa = nBa; dBb = nBb;
    }
    __syncthreads();

    // prefetch V chunk 0 early (latency hides behind softmax)
    float4 vp0 = *(const float4*)&vbase[t*4];
    float4 vp1 = *(const float4*)&vbase[(t + 512)*4];
    bool vv0 = true, vv1 = true;

    // ================= softmax (one row per warp) + attn write =================
    int w = t >> 5, lane = t & 31;
    {
        int rr = w;
        int qg = q0 + rr;
        if (qg < EE) {
            float* row = sc + rr*SC_LD;
            float m = -3.4e38f;
            for (int k = lane*4; k < EE; k += 128) {
                float4 v = *(const float4*)&row[k];
                m = fmaxf(m, fmaxf(fmaxf(v.x, v.y), fmaxf(v.z, v.w)));
            }
            m = warp_max(m);
            float sum = 0.f;
            for (int k = lane*4; k < EE; k += 128) {
                float4 v = *(float4*)&row[k];
                v.x = __expf(v.x - m); v.y = __expf(v.y - m);
                v.z = __expf(v.z - m); v.w = __expf(v.w - m);
                *(float4*)&row[k] = v;
                sum += (v.x + v.y) + (v.z + v.w);
            }
            sum = warp_sum(sum);
            float inv = 1.f / sum;
            if (lane == 0) flag[rr] = (m < -1e8f) ? 0.f : 1.f;
            long long obase = (long long)O_ATTN + (long long)(bh*EE + qg)*EE;
            for (int k = lane*4; k < EE; k += 128) {
                float4 v = *(float4*)&row[k];
                v.x *= inv; v.y *= inv; v.z *= inv; v.w *= inv;
                *(float4*)&out[obase + k] = v;
                *(float4*)&row[k] = v;
            }
        } else {
            if (lane == 0) flag[rr] = 0.f;
        }
    }
    __syncthreads();

    // column sums -> one REDG per column
    for (int k = t; k < EE; k += 512) {
        float s = 0.f;
        #pragma unroll
        for (int r = 0; r < 16; r++) s += sc[r*SC_LD + k] * flag[r];
        atomicAdd(&g_asum[b*EE + k], s);
    }

    // ================= AV =================
    // thread: ksub = t>>7 (k quarter), cells (q in {qp,qp+8}) x (d in {dp,dp+16})
    int tl = t & 127, ksub = t >> 7;
    int dp = tl & 15, qp = tl >> 4;
    ull cAa = 0, cAb = 0, cBa = 0, cBb = 0;

    for (int c = 0; c < 12; c++) {
        int kc = c * 128, cw = min(128, EE - kc);
        float* bp = (c & 1) ? buf1 : buf0;
        // store current chunk V transposed [d][k], swizzled
        if (vv0) {
            int kr = t >> 3, d0 = (t & 7)*4;
            int u2 = (kr >> 1), klo = kr & 1;
            bp[(d0+0)*128 + ((u2 ^ ((d0+0)&15))<<1) + klo] = vp0.x;
            bp[(d0+1)*128 + ((u2 ^ ((d0+1)&15))<<1) + klo] = vp0.y;
            bp[(d0+2)*128 + ((u2 ^ ((d0+2)&15))<<1) + klo] = vp0.z;
            bp[(d0+3)*128 + ((u2 ^ ((d0+3)&15))<<1) + klo] = vp0.w;
        }
        if (vv1) {
            int i4 = t + 512;
            int kr = i4 >> 3, d0 = (i4 & 7)*4;
            int u2 = (kr >> 1), klo = kr & 1;
            bp[(d0+0)*128 + ((u2 ^ ((d0+0)&15))<<1) + klo] = vp1.x;
            bp[(d0+1)*128 + ((u2 ^ ((d0+1)&15))<<1) + klo] = vp1.y;
            bp[(d0+2)*128 + ((u2 ^ ((d0+2)&15))<<1) + klo] = vp1.z;
            bp[(d0+3)*128 + ((u2 ^ ((d0+3)&15))<<1) + klo] = vp1.w;
        }
        __syncthreads();

        // prefetch next V chunk
        float4 n0 = vp0, n1 = vp1; bool w0 = false, w1 = false;
        if (c < 11) {
            int kc2 = kc + 128, cw2 = min(128, EE - kc2);
            w0 = (t       < cw2*8);
            w1 = (t + 512 < cw2*8);
            if (w0) n0 = *(const float4*)&vbase[kc2*32 + t*4];
            if (w1) n1 = *(const float4*)&vbase[kc2*32 + (t+512)*4];
        }

        const ull* vrA = (const ull*)bp + dp*64 + ksub*16;
        const ull* vrB = (const ull*)bp + (dp+16)*64 + ksub*16;
        const ull* sA  = (const ull*)sc + qp*(SC_LD/2)     + (kc>>1) + ksub*16;
        const ull* sB  = (const ull*)sc + (qp+8)*(SC_LD/2) + (kc>>1) + ksub*16;

        if (cw == 128) {
            #pragma unroll
            for (int j = 0; j < 16; j++) {
                ull va = vrA[j ^ dp];
                ull vb = vrB[j ^ dp];
                ull a2A = sA[j];
                ull a2B = sB[j];
                fma2(cAa, a2A, va); fma2(cAb, a2A, vb);
                fma2(cBa, a2B, va); fma2(cBb, a2B, vb);
            }
        } else {
            int rem = cw - ksub*32;
            int npair = (rem >= 32) ? 16 : ((rem > 0) ? (rem >> 1) : 0);
            for (int j = 0; j < npair; j++) {
                ull va = vrA[j ^ dp];
                ull vb = vrB[j ^ dp];
                ull a2A = sA[j];
                ull a2B = sB[j];
                fma2(cAa, a2A, va); fma2(cAb, a2A, vb);
                fma2(cBa, a2B, va); fma2(cBb, a2B, vb);
            }
        }
        vp0 = n0; vp1 = n1; vv0 = w0; vv1 = w1;
    }

    // combine the 4 k-partitions via smem
    __syncthreads();
    {
        float* part = buf0;   // [ksub][q][d] = 4*16*32
        part[ksub*512 + qp*32       + dp]      = f2sum(cAa);
        part[ksub*512 + qp*32       + dp + 16] = f2sum(cAb);
        part[ksub*512 + (qp+8)*32   + dp]      = f2sum(cBa);
        part[ksub*512 + (qp+8)*32   + dp + 16] = f2sum(cBb);
    }
    __syncthreads();
    {
        float* part = buf0;
        int q = t >> 5, dd = t & 31;
        float s = part[q*32 + dd] + part[512 + q*32 + dd]
                + part[1024 + q*32 + dd] + part[1536 + q*32 + dd];
        if (q0 + q < EE) g_o[(b*EE + q0 + q)*DD + h*32 + dd] = s;
    }
}

// ---------------- K3: FC + residual + transpose-out ----------------
__global__ void __launch_bounds__(256) fc_kernel(
    const float* __restrict__ x, const float* __restrict__ Wfc,
    float* __restrict__ out)
{
    __shared__ __align__(16) float osm[256*8];   // [d][r]
    int b  = blockIdx.y;
    int e0 = blockIdx.x * 8;
    int t  = threadIdx.x;

    for (int i = t; i < 2048; i += 256) {
        int r = i >> 8, d = i & 255;
        int e = e0 + r;
        osm[d*8 + r] = (e < EE) ? g_o[(b*EE + e)*DD + d] : 0.f;
    }
    __syncthreads();

    int j = t;
    const float* xb = x + b*DD*EE + j*EE;
    float acc[8];
    #pragma unroll
    for (int r = 0; r < 8; r++) {
        int e = e0 + r;
        acc[r] = (e < EE) ? xb[e] : 0.f;   // residual
    }
    #pragma unroll 4
    for (int d = 0; d < 256; d++) {
        float wv = Wfc[d*256 + j];
        float4 o0 = *(const float4*)&osm[d*8];
        float4 o1 = *(const float4*)&osm[d*8 + 4];
        acc[0] += o0.x*wv; acc[1] += o0.y*wv; acc[2] += o0.z*wv; acc[3] += o0.w*wv;
        acc[4] += o1.x*wv; acc[5] += o1.y*wv; acc[6] += o1.z*wv; acc[7] += o1.w*wv;
    }
    float* ob = out + b*DD*EE + j*EE + e0;
    if (e0 + 8 <= EE) {
        *(float4*)ob       = make_float4(acc[0], acc[1], acc[2], acc[3]);
        *(float4*)(ob + 4) = make_float4(acc[4], acc[5], acc[6], acc[7]);
    } else {
        for (int r = 0; r < 8; r++)
            if (e0 + r < EE) ob[r] = acc[r];
    }
}

// ---------------- K4: attn_per_edge ----------------
__global__ void finalize_kernel(float* __restrict__ out) {
    int i = blockIdx.x * 256 + threadIdx.x;
    if (i < BB*EE) {
        out[O_APE + i] = g_asum[i] / (float)g_acnt[i];
    }
}

// ---------------- launch ----------------
extern "C" void kernel_launch(void* const* d_in, const int* in_sizes, int n_in,
                              void* d_out, int out_size)
{
    const float* x    = (const float*)d_in[0];
    const int*   dist = (const int*)  d_in[1];
    const float* Wq   = (const float*)d_in[2];
    const float* Wk   = (const float*)d_in[3];
    const float* Wv   = (const float*)d_in[4];
    const float* Wfc  = (const float*)d_in[5];
    const float* lnw  = (const float*)d_in[6];
    const float* lnb  = (const float*)d_in[7];
    const float* rpr  = (const float*)d_in[8];
    float* out = (float*)d_out;

    cudaFuncSetAttribute(attn_kernel,
        cudaFuncAttributeMaxDynamicSharedMemorySize, SMEM_ATTN);

    zero_kernel<<<24, 256>>>();

    dim3 gc(24, 8);
    count_kernel<<<gc, 256>>>(dist);

    dim3 g1(188, BB);
    proj_kernel<<<g1, 256>>>(x, Wq, Wk, Wv, lnw, lnb, rpr);

    dim3 g2(94, HH, BB);
    attn_kernel<<<g2, 512, SMEM_ATTN>>>(dist, out);

    dim3 g3(188, BB);
    fc_kernel<<<g3, 256>>>(x, Wfc, out);

    finalize_kernel<<<24, 256>>>(out);
}

// round 4
// speedup vs baseline: 2.9979x; 1.0723x over previous
#include <cuda_runtime.h>

#define BB 4
#define EE 1500
#define DD 256
#define HH 8
#define DK 32

#define O_ATTN 1536000
#define O_APE  73536000

typedef unsigned long long ull;

// ---------------- scratch (no allocation allowed) ----------------
__device__ float g_q[BB*HH*EE*DK];     // scaled q, [b,h,e,dk]
__device__ float g_k[BB*HH*EE*DK];
__device__ float g_v[BB*HH*EE*DK];
__device__ float g_qdr[BB*HH*EE*8];    // q . base_rpr[p], p padded to 8
__device__ float g_o[BB*EE*DD];        // attention output pre-FC, [b,e,h*32+d]
__device__ float g_asum[BB*EE];
__device__ int   g_acnt[BB*EE];

__device__ __forceinline__ float warp_sum(float v) {
    #pragma unroll
    for (int o = 16; o; o >>= 1) v += __shfl_xor_sync(0xffffffffu, v, o);
    return v;
}
__device__ __forceinline__ float warp_max(float v) {
    #pragma unroll
    for (int o = 16; o; o >>= 1) v = fmaxf(v, __shfl_xor_sync(0xffffffffu, v, o));
    return v;
}

// packed f32x2 helpers (sm_100+)
__device__ __forceinline__ void fma2(ull &d, ull a, ull b) {
    asm("fma.rn.f32x2 %0, %1, %2, %0;" : "+l"(d) : "l"(a), "l"(b));
}
__device__ __forceinline__ ull f2add(ull a, ull b) {
    ull d;
    asm("add.rn.f32x2 %0, %1, %2;" : "=l"(d) : "l"(a), "l"(b));
    return d;
}
__device__ __forceinline__ float f2sum(ull u) {
    float lo, hi;
    asm("mov.b64 {%0,%1}, %2;" : "=f"(lo), "=f"(hi) : "l"(u));
    return lo + hi;
}
__device__ __forceinline__ ull packf2(float x, float y) {
    ull u;
    asm("mov.b64 %0, {%1,%2};" : "=l"(u) : "f"(x), "f"(y));
    return u;
}

// ---------------- K0: zero accumulators ----------------
__global__ void zero_kernel() {
    int i = blockIdx.x * 256 + threadIdx.x;
    if (i < BB*EE) { g_asum[i] = 0.f; g_acnt[i] = 0; }
}

// ---------------- K0b: valid-edge counts from dist ----------------
__global__ void count_kernel(const int* __restrict__ dist) {
    int i = blockIdx.x * 256 + threadIdx.x;   // b*EE + e
    if (i >= BB*EE) return;
    int b = i / EE, e = i - b*EE;
    int q0 = blockIdx.y * 188;
    int q1 = min(EE, q0 + 188);
    const int* dp = dist + (long long)b*EE*EE + e;
    int c = 0;
    #pragma unroll 4
    for (int q = q0; q < q1; q++) c += (dp[q*EE] <= 3) ? 1 : 0;
    atomicAdd(&g_acnt[i], c);
}

// ---------------- K1: layernorm + QKV projections + q.rpr ----------------
__global__ void __launch_bounds__(256) proj_kernel(
    const float* __restrict__ x,
    const float* __restrict__ Wq, const float* __restrict__ Wk,
    const float* __restrict__ Wv,
    const float* __restrict__ lnw, const float* __restrict__ lnb,
    const float* __restrict__ rpr)
{
    __shared__ __align__(16) float ssm[256*8];   // [d][r] raw input rows
    __shared__ __align__(16) float nsm[256*8];   // [d][r] layernormed rows
    int b  = blockIdx.y;
    int e0 = blockIdx.x * 8;
    int t  = threadIdx.x;
    const float* xb = x + b*(DD*EE);

    for (int i = t; i < 2048; i += 256) {
        int d = i >> 3, r = i & 7;
        int e = e0 + r;
        ssm[i] = (e < EE) ? xb[d*EE + e] : 0.f;
    }
    __syncthreads();

    int w = t >> 5, lane = t & 31;
    {   // layernorm of row w (one row per warp)
        float s = 0.f;
        #pragma unroll
        for (int i = 0; i < 8; i++) s += ssm[(lane + 32*i)*8 + w];
        s = warp_sum(s);
        float mu = s * (1.f/256.f);
        float vs = 0.f;
        #pragma unroll
        for (int i = 0; i < 8; i++) {
            float dlt = ssm[(lane + 32*i)*8 + w] - mu;
            vs += dlt*dlt;
        }
        vs = warp_sum(vs);
        float rstd = rsqrtf(vs * (1.f/256.f) + 1e-6f);
        #pragma unroll
        for (int i = 0; i < 8; i++) {
            int d = lane + 32*i;
            nsm[d*8 + w] = (ssm[d*8 + w] - mu) * rstd * lnw[d] + lnb[d];
        }
    }
    __syncthreads();

    int j = t;
    float aq[8], ak[8], av[8];
    #pragma unroll
    for (int r = 0; r < 8; r++) { aq[r] = 0.f; ak[r] = 0.f; av[r] = 0.f; }

    #pragma unroll 4
    for (int d = 0; d < 256; d++) {
        float wq = Wq[d*256 + j];
        float wk = Wk[d*256 + j];
        float wv = Wv[d*256 + j];
        float4 s0 = *(const float4*)&ssm[d*8];
        float4 s1 = *(const float4*)&ssm[d*8 + 4];
        float4 n0 = *(const float4*)&nsm[d*8];
        float4 n1 = *(const float4*)&nsm[d*8 + 4];
        aq[0] += n0.x*wq; aq[1] += n0.y*wq; aq[2] += n0.z*wq; aq[3] += n0.w*wq;
        aq[4] += n1.x*wq; aq[5] += n1.y*wq; aq[6] += n1.z*wq; aq[7] += n1.w*wq;
        ak[0] += s0.x*wk; ak[1] += s0.y*wk; ak[2] += s0.z*wk; ak[3] += s0.w*wk;
        ak[4] += s1.x*wk; ak[5] += s1.y*wk; ak[6] += s1.z*wk; ak[7] += s1.w*wk;
        av[0] += s0.x*wv; av[1] += s0.y*wv; av[2] += s0.z*wv; av[3] += s0.w*wv;
        av[4] += s1.x*wv; av[5] += s1.y*wv; av[6] += s1.z*wv; av[7] += s1.w*wv;
    }

    int h = j >> 5, dk = j & 31;
    const float inv_sqrt_dk = 0.17677669529663687f;  // 1/sqrt(32)
    float qsv[8];
    #pragma unroll
    for (int r = 0; r < 8; r++) qsv[r] = aq[r] * inv_sqrt_dk;

    #pragma unroll
    for (int r = 0; r < 8; r++) {
        int e = e0 + r;
        if (e < EE) {
            int base = ((b*HH + h)*EE + e)*32 + dk;
            g_q[base] = qsv[r];
            g_k[base] = ak[r];
            g_v[base] = av[r];
        }
    }

    #pragma unroll
    for (int p = 0; p < 6; p++) {
        float rv = rpr[p*32 + lane];
        #pragma unroll
        for (int r = 0; r < 8; r++) {
            float pv = warp_sum(qsv[r] * rv);
            if (lane == 0 && (e0 + r) < EE)
                g_qdr[((b*HH + h)*EE + (e0 + r))*8 + p] = pv;
        }
    }
}

// ---------------- K2: attention ----------------
#define SC_LD 1504
// floats: sc 24064 + buf0 4096 + buf1 4096 + qsm 512 + qdr 128 + flag 16
#define SMEM_ATTN ((16*SC_LD + 4096 + 4096 + 512 + 128 + 16)*4)

__global__ void __launch_bounds__(512, 1) attn_kernel(
    const int* __restrict__ dist, float* __restrict__ out)
{
    extern __shared__ __align__(16) float sm[];
    float* sc   = sm;                    // 16 x 1504 scores -> attn (normalized)
    float* buf0 = sc + 16*SC_LD;         // 16KB: K chunk [k][d] / V chunk [k][d]
    float* buf1 = buf0 + 4096;
    float* qsm  = buf1 + 4096;           // 16 x 32 scaled q
    float* qdr  = qsm + 512;             // 16 x 8 bias table
    float* flag = qdr + 128;             // 16 row-valid flags

    int qt = blockIdx.x, h = blockIdx.y, b = blockIdx.z;
    int q0 = qt * 16;
    int t  = threadIdx.x;
    int bh = b*HH + h;
    const float* kbase = g_k + bh*(EE*32);
    const float* vbase = g_v + bh*(EE*32);

    for (int i = t; i < 16*32; i += 512) {
        int qg = q0 + (i >> 5);
        qsm[i] = (qg < EE) ? g_q[(bh*EE + qg)*32 + (i & 31)] : 0.f;
    }
    if (t < 16*8) {
        int qg = q0 + (t >> 3);
        qdr[t] = (qg < EE) ? g_qdr[(bh*EE + qg)*8 + (t & 7)] : 0.f;
    }
    __syncthreads();

    // ================= score phase =================
    const int* distb = dist + (long long)b*(EE*EE);
    int kcA = t & 63;
    int qpA = t >> 6, qpB = qpA + 8;
    int qgA = q0 + qpA, qgB = q0 + qpB;

    // Q rows into registers (broadcast LDS64, once)
    ull qA[16], qB[16];
    {
        const ull* qrA = (const ull*)(qsm + qpA*32);
        const ull* qrB = (const ull*)(qsm + qpB*32);
        #pragma unroll
        for (int j = 0; j < 16; j++) { qA[j] = qrA[j]; qB[j] = qrB[j]; }
    }

    int xA8 = (kcA & 15);   // swizzle mask (same for kcA and kcA+64)

    // prologue: prefetch chunk 0 (K + dist)
    float4 p0, p1; bool v0, v1;
    int dAa, dAb, dBa, dBb;
    {
        v0 = true; v1 = true;
        p0 = *(const float4*)&kbase[t*4];
        p1 = *(const float4*)&kbase[(t + 512)*4];
        int kgA = kcA, kgB = kcA + 64;
        dAa = (qgA < EE) ? distb[qgA*EE + kgA] : 99;
        dAb = (qgA < EE) ? distb[qgA*EE + kgB] : 99;
        dBa = (qgB < EE) ? distb[qgB*EE + kgA] : 99;
        dBb = (qgB < EE) ? distb[qgB*EE + kgB] : 99;
    }

    for (int c = 0; c < 12; c++) {
        int kc = c * 128;
        float* bp = (c & 1) ? buf1 : buf0;
        // store current chunk K into smem, swizzled [k][d]
        if (v0) {
            int kr = t >> 3, u0 = (t & 7)*2, xm = kr & 15;
            *(ull*)&bp[kr*32 + ((u0     ^ xm)<<1)] = packf2(p0.x, p0.y);
            *(ull*)&bp[kr*32 + (((u0+1) ^ xm)<<1)] = packf2(p0.z, p0.w);
        }
        if (v1) {
            int i4 = t + 512;
            int kr = i4 >> 3, u0 = (i4 & 7)*2, xm = kr & 15;
            *(ull*)&bp[kr*32 + ((u0     ^ xm)<<1)] = packf2(p1.x, p1.y);
            *(ull*)&bp[kr*32 + (((u0+1) ^ xm)<<1)] = packf2(p1.z, p1.w);
        }
        __syncthreads();

        // prefetch chunk c+1
        float4 n0 = p0, n1 = p1; bool w0 = false, w1 = false;
        int nAa = 99, nAb = 99, nBa = 99, nBb = 99;
        if (c < 11) {
            int kc2 = kc + 128, cw2 = min(128, EE - kc2);
            w0 = (t       < cw2*8);
            w1 = (t + 512 < cw2*8);
            if (w0) n0 = *(const float4*)&kbase[kc2*32 + t*4];
            if (w1) n1 = *(const float4*)&kbase[kc2*32 + (t+512)*4];
            int kg2A = kc2 + kcA, kg2B = kg2A + 64;
            if (qgA < EE && kg2A < EE) nAa = distb[qgA*EE + kg2A];
            if (qgA < EE && kg2B < EE) nAb = distb[qgA*EE + kg2B];
            if (qgB < EE && kg2A < EE) nBa = distb[qgB*EE + kg2A];
            if (qgB < EE && kg2B < EE) nBb = distb[qgB*EE + kg2B];
        }

        // compute 4 cells over 32 d (16 f32x2 pairs)
        const ull* rA = (const ull*)bp + kcA*16;
        const ull* rB = rA + 64*16;
        ull aAA = 0, aAB = 0, aBA = 0, aBB = 0;
        #pragma unroll
        for (int j = 0; j < 16; j++) {
            ull ka = rA[j ^ xA8];
            ull kb = rB[j ^ xA8];
            fma2(aAA, qA[j], ka); fma2(aAB, qA[j], kb);
            fma2(aBA, qB[j], ka); fma2(aBB, qB[j], kb);
        }

        // epilogue: bias + mask + store
        int kgA = kc + kcA, kgB = kgA + 64;
        if (kgA < EE) {
            float s = -1e9f;
            if (dAa <= 3) s = f2sum(aAA) + qdr[qpA*8 + dAa];
            sc[qpA*SC_LD + kgA] = s;
            s = -1e9f;
            if (dBa <= 3) s = f2sum(aBA) + qdr[qpB*8 + dBa];
            sc[qpB*SC_LD + kgA] = s;
        }
        if (kgB < EE) {
            float s = -1e9f;
            if (dAb <= 3) s = f2sum(aAB) + qdr[qpA*8 + dAb];
            sc[qpA*SC_LD + kgB] = s;
            s = -1e9f;
            if (dBb <= 3) s = f2sum(aBB) + qdr[qpB*8 + dBb];
            sc[qpB*SC_LD + kgB] = s;
        }

        p0 = n0; p1 = n1; v0 = w0; v1 = w1;
        dAa = nAa; dAb = nAb; dBa = nBa; dBb = nBb;
    }
    __syncthreads();

    // prefetch V chunk 0 early (latency hides behind softmax)
    float4 vp0 = *(const float4*)&vbase[t*4];
    float4 vp1 = *(const float4*)&vbase[(t + 512)*4];
    bool vv0 = true, vv1 = true;

    // ================= softmax (one row per warp) + attn write =================
    int w = t >> 5, lane = t & 31;
    {
        int rr = w;
        int qg = q0 + rr;
        if (qg < EE) {
            float* row = sc + rr*SC_LD;
            float m = -3.4e38f;
            for (int k = lane*4; k < EE; k += 128) {
                float4 v = *(const float4*)&row[k];
                m = fmaxf(m, fmaxf(fmaxf(v.x, v.y), fmaxf(v.z, v.w)));
            }
            m = warp_max(m);
            float sum = 0.f;
            for (int k = lane*4; k < EE; k += 128) {
                float4 v = *(float4*)&row[k];
                v.x = __expf(v.x - m); v.y = __expf(v.y - m);
                v.z = __expf(v.z - m); v.w = __expf(v.w - m);
                *(float4*)&row[k] = v;
                sum += (v.x + v.y) + (v.z + v.w);
            }
            sum = warp_sum(sum);
            float inv = 1.f / sum;
            if (lane == 0) flag[rr] = (m < -1e8f) ? 0.f : 1.f;
            long long obase = (long long)O_ATTN + (long long)(bh*EE + qg)*EE;
            for (int k = lane*4; k < EE; k += 128) {
                float4 v = *(float4*)&row[k];
                v.x *= inv; v.y *= inv; v.z *= inv; v.w *= inv;
                *(float4*)&out[obase + k] = v;
                *(float4*)&row[k] = v;
            }
        } else {
            if (lane == 0) flag[rr] = 0.f;
        }
    }
    __syncthreads();

    // column sums -> one REDG per column
    for (int k = t; k < EE; k += 512) {
        float s = 0.f;
        #pragma unroll
        for (int r = 0; r < 16; r++) s += sc[r*SC_LD + k] * flag[r];
        atomicAdd(&g_asum[b*EE + k], s);
    }

    // ================= AV =================
    // thread = (qgrp: 4 q-rows) x (dgrp: 8 d-values) x (lane: 4-k slice)
    // lane = t&31 (k slice), dgrp = (t>>5)&3, qgrp = t>>7
    // f32x2 pairs along d; V stays [k][d] (natural layout, float4 = 4 d)
    int dgrp = (t >> 5) & 3;
    int qgrp = t >> 7;
    ull acc[4][4];   // [q-slot][d-pair]  d = 8*dgrp + p*2 + {0,1}
    #pragma unroll
    for (int s = 0; s < 4; s++)
        #pragma unroll
        for (int p = 0; p < 4; p++) acc[s][p] = 0;

    for (int c = 0; c < 12; c++) {
        int kc = c * 128, cw = min(128, EE - kc);
        float4* bp4 = (float4*)((c & 1) ? buf1 : buf0);
        // store V chunk [k][d] as float4 units with 2-level swizzle
        if (vv0) {
            int kr = t >> 3, u = t & 7;
            bp4[kr*8 + (u ^ (kr & 7) ^ ((kr >> 3) & 7))] = vp0;
        }
        if (vv1) {
            int i4 = t + 512;
            int kr = i4 >> 3, u = i4 & 7;
            bp4[kr*8 + (u ^ (kr & 7) ^ ((kr >> 3) & 7))] = vp1;
        }
        __syncthreads();

        // prefetch next V chunk
        float4 n0 = vp0, n1 = vp1; bool w0 = false, w1 = false;
        if (c < 11) {
            int kc2 = kc + 128, cw2 = min(128, EE - kc2);
            w0 = (t       < cw2*8);
            w1 = (t + 512 < cw2*8);
            if (w0) n0 = *(const float4*)&vbase[kc2*32 + t*4];
            if (w1) n1 = *(const float4*)&vbase[kc2*32 + (t+512)*4];
        }

        if (4*lane < cw) {
            // attn values: one coalesced LDS128 per q row (4 k values)
            float4 a0 = *(const float4*)&sc[(qgrp     )*SC_LD + kc + 4*lane];
            float4 a1 = *(const float4*)&sc[(qgrp +  4)*SC_LD + kc + 4*lane];
            float4 a2 = *(const float4*)&sc[(qgrp +  8)*SC_LD + kc + 4*lane];
            float4 a3 = *(const float4*)&sc[(qgrp + 12)*SC_LD + kc + 4*lane];
            #pragma unroll
            for (int kk = 0; kk < 4; kk++) {
                int k = 4*lane + kk;
                int sw = (k & 7) ^ ((k >> 3) & 7);
                float4 vA = bp4[k*8 + ((2*dgrp    ) ^ sw)];
                float4 vB = bp4[k*8 + ((2*dgrp + 1) ^ sw)];
                ull vA0 = packf2(vA.x, vA.y), vA1 = packf2(vA.z, vA.w);
                ull vB0 = packf2(vB.x, vB.y), vB1 = packf2(vB.z, vB.w);
                float f0 = (kk==0)?a0.x:(kk==1)?a0.y:(kk==2)?a0.z:a0.w;
                float f1 = (kk==0)?a1.x:(kk==1)?a1.y:(kk==2)?a1.z:a1.w;
                float f2v = (kk==0)?a2.x:(kk==1)?a2.y:(kk==2)?a2.z:a2.w;
                float f3 = (kk==0)?a3.x:(kk==1)?a3.y:(kk==2)?a3.z:a3.w;
                ull s0 = packf2(f0, f0);
                ull s1 = packf2(f1, f1);
                ull s2 = packf2(f2v, f2v);
                ull s3 = packf2(f3, f3);
                fma2(acc[0][0], s0, vA0); fma2(acc[0][1], s0, vA1);
                fma2(acc[0][2], s0, vB0); fma2(acc[0][3], s0, vB1);
                fma2(acc[1][0], s1, vA0); fma2(acc[1][1], s1, vA1);
                fma2(acc[1][2], s1, vB0); fma2(acc[1][3], s1, vB1);
                fma2(acc[2][0], s2, vA0); fma2(acc[2][1], s2, vA1);
                fma2(acc[2][2], s2, vB0); fma2(acc[2][3], s2, vB1);
                fma2(acc[3][0], s3, vA0); fma2(acc[3][1], s3, vA1);
                fma2(acc[3][2], s3, vB0); fma2(acc[3][3], s3, vB1);
            }
        }
        vp0 = n0; vp1 = n1; vv0 = w0; vv1 = w1;
        __syncthreads();
    }

    // reduce the 32 k-slices within each warp (lane = k-slice)
    #pragma unroll
    for (int s = 0; s < 4; s++) {
        #pragma unroll
        for (int p = 0; p < 4; p++) {
            ull a = acc[s][p];
            #pragma unroll
            for (int o = 16; o; o >>= 1)
                a = f2add(a, __shfl_xor_sync(0xffffffffu, a, o));
            acc[s][p] = a;
        }
    }
    if (lane == 0) {
        #pragma unroll
        for (int s = 0; s < 4; s++) {
            int qg = q0 + qgrp + 4*s;
            if (qg < EE) {
                ull* op = (ull*)&g_o[(b*EE + qg)*DD + h*32 + 8*dgrp];
                op[0] = acc[s][0]; op[1] = acc[s][1];
                op[2] = acc[s][2]; op[3] = acc[s][3];
            }
        }
    }
}

// ---------------- K3: FC + residual + transpose-out ----------------
__global__ void __launch_bounds__(256) fc_kernel(
    const float* __restrict__ x, const float* __restrict__ Wfc,
    float* __restrict__ out)
{
    __shared__ __align__(16) float osm[256*8];   // [d][r]
    int b  = blockIdx.y;
    int e0 = blockIdx.x * 8;
    int t  = threadIdx.x;

    for (int i = t; i < 2048; i += 256) {
        int r = i >> 8, d = i & 255;
        int e = e0 + r;
        osm[d*8 + r] = (e < EE) ? g_o[(b*EE + e)*DD + d] : 0.f;
    }
    __syncthreads();

    int j = t;
    const float* xb = x + b*DD*EE + j*EE;
    float acc[8];
    #pragma unroll
    for (int r = 0; r < 8; r++) {
        int e = e0 + r;
        acc[r] = (e < EE) ? xb[e] : 0.f;   // residual
    }
    #pragma unroll 4
    for (int d = 0; d < 256; d++) {
        float wv = Wfc[d*256 + j];
        float4 o0 = *(const float4*)&osm[d*8];
        float4 o1 = *(const float4*)&osm[d*8 + 4];
        acc[0] += o0.x*wv; acc[1] += o0.y*wv; acc[2] += o0.z*wv; acc[3] += o0.w*wv;
        acc[4] += o1.x*wv; acc[5] += o1.y*wv; acc[6] += o1.z*wv; acc[7] += o1.w*wv;
    }
    float* ob = out + b*DD*EE + j*EE + e0;
    if (e0 + 8 <= EE) {
        *(float4*)ob       = make_float4(acc[0], acc[1], acc[2], acc[3]);
        *(float4*)(ob + 4) = make_float4(acc[4], acc[5], acc[6], acc[7]);
    } else {
        for (int r = 0; r < 8; r++)
            if (e0 + r < EE) ob[r] = acc[r];
    }
}

// ---------------- K4: attn_per_edge ----------------
__global__ void finalize_kernel(float* __restrict__ out) {
    int i = blockIdx.x * 256 + threadIdx.x;
    if (i < BB*EE) {
        out[O_APE + i] = g_asum[i] / (float)g_acnt[i];
    }
}

// ---------------- launch ----------------
extern "C" void kernel_launch(void* const* d_in, const int* in_sizes, int n_in,
                              void* d_out, int out_size)
{
    const float* x    = (const float*)d_in[0];
    const int*   dist = (const int*)  d_in[1];
    const float* Wq   = (const float*)d_in[2];
    const float* Wk   = (const float*)d_in[3];
    const float* Wv   = (const float*)d_in[4];
    const float* Wfc  = (const float*)d_in[5];
    const float* lnw  = (const float*)d_in[6];
    const float* lnb  = (const float*)d_in[7];
    const float* rpr  = (const float*)d_in[8];
    float* out = (float*)d_out;

    cudaFuncSetAttribute(attn_kernel,
        cudaFuncAttributeMaxDynamicSharedMemorySize, SMEM_ATTN);

    zero_kernel<<<24, 256>>>();

    dim3 gc(24, 8);
    count_kernel<<<gc, 256>>>(dist);

    dim3 g1(188, BB);
    proj_kernel<<<g1, 256>>>(x, Wq, Wk, Wv, lnw, lnb, rpr);

    dim3 g2(94, HH, BB);
    attn_kernel<<<g2, 512, SMEM_ATTN>>>(dist, out);

    dim3 g3(188, BB);
    fc_kernel<<<g3, 256>>>(x, Wfc, out);

    finalize_kernel<<<24, 256>>>(out);
}